// round 9
// baseline (speedup 1.0000x reference)
#include <cuda_runtime.h>
#include <cuda_bf16.h>
#include <math.h>

// Problem constants (fixed by the reference)
#define NN 50000
#define EE 400000
// IN=128, H1=128, HEADS=8, HID=16, OUT=128, EDIM=32

typedef unsigned long long u64;

__device__ __forceinline__ u64 pack2(float lo, float hi) {
    u64 r;
    asm("mov.b64 %0, {%1, %2};" : "=l"(r) : "r"(__float_as_uint(lo)), "r"(__float_as_uint(hi)));
    return r;
}
__device__ __forceinline__ void unpack2(u64 v, float& lo, float& hi) {
    unsigned int a, b;
    asm("mov.b64 {%0, %1}, %2;" : "=r"(a), "=r"(b) : "l"(v));
    lo = __uint_as_float(a); hi = __uint_as_float(b);
}
__device__ __forceinline__ void fma2(u64& d, u64 a, u64 b) {
    asm("fma.rn.f32x2 %0, %1, %2, %3;" : "=l"(d) : "l"(a), "l"(b), "l"(d));
}

// ---------------- scratch (static device globals; no allocation) -------------
static __device__ float g_Q[NN * 128];
static __device__ float g_K[NN * 128];
static __device__ float g_V[NN * 128];
static __device__ float g_S[NN * 128];          // skip term x@Ws+bs
static __device__ float g_H[NN * 128];          // layer1 output h
static __device__ int   g_src[EE];
static __device__ int   g_dst[EE];
static __device__ int   g_deg[NN];
static __device__ int   g_rowptr[NN + 1];
static __device__ int   g_cursor[NN];
static __device__ int2  g_csr[EE];              // (src, eid)
static __device__ int   g_is64;

// ---------------- dtype sniffing for edge_index ------------------------------
__global__ void detect_idx_kernel(const unsigned int* __restrict__ p) {
    __shared__ unsigned int sh[256];
    unsigned int acc = 0;
    for (int i = threadIdx.x; i < 4096; i += 256) acc |= p[2 * i + 1];
    sh[threadIdx.x] = acc;
    __syncthreads();
    for (int s = 128; s > 0; s >>= 1) {
        if (threadIdx.x < s) sh[threadIdx.x] |= sh[threadIdx.x + s];
        __syncthreads();
    }
    if (threadIdx.x == 0) g_is64 = (sh[0] == 0u) ? 1 : 0;
}

__global__ void extract_idx_kernel(const void* __restrict__ p) {
    int e = blockIdx.x * blockDim.x + threadIdx.x;
    if (e >= EE) return;
    if (g_is64) {
        const long long* q = (const long long*)p;
        g_src[e] = (int)q[e];
        g_dst[e] = (int)q[EE + e];
    } else {
        const int* q = (const int*)p;
        g_src[e] = q[e];
        g_dst[e] = q[EE + e];
    }
}

// ---------------- CSR build --------------------------------------------------
__global__ void zero_deg_kernel() {
    int i = blockIdx.x * blockDim.x + threadIdx.x;
    if (i < NN) g_deg[i] = 0;
}

__global__ void hist_kernel() {
    int e = blockIdx.x * blockDim.x + threadIdx.x;
    if (e < EE) atomicAdd(&g_deg[g_dst[e]], 1);
}

__global__ void __launch_bounds__(1024) csr_scan_kernel() {
    __shared__ int ssum[1024];
    int t = threadIdx.x;
    const int CH = (NN + 1023) / 1024; // 49
    int start = t * CH;
    int s = 0;
    for (int i = 0; i < CH; i++) {
        int idx = start + i;
        if (idx < NN) s += g_deg[idx];
    }
    ssum[t] = s;
    __syncthreads();
    for (int off = 1; off < 1024; off <<= 1) {
        int v = (t >= off) ? ssum[t - off] : 0;
        __syncthreads();
        ssum[t] += v;
        __syncthreads();
    }
    int run = (t == 0) ? 0 : ssum[t - 1];
    for (int i = 0; i < CH; i++) {
        int idx = start + i;
        if (idx < NN) {
            g_rowptr[idx] = run;
            g_cursor[idx] = run;
            run += g_deg[idx];
        }
    }
    if (t == 1023) g_rowptr[NN] = run;
}

__global__ void csr_scatter_kernel() {
    int e = blockIdx.x * blockDim.x + threadIdx.x;
    if (e >= EE) return;
    int d = g_dst[e];
    int pos = atomicAdd(&g_cursor[d], 1);
    g_csr[pos] = make_int2(g_src[e], e);
}

// ---------------- fused node GEMM: 4 outputs, 128x128 tile -------------------
// Pack-free inner loop: A staged in smem as duplicated (a,a) u64 splats;
// W staged as floats, read as natural f32x2 column pairs.
// Per kk: 4 LDS.128 (a) + 2 LDS.128 (w) + 32 FFMA2, no ALU packs.
__global__ void __launch_bounds__(256) gemm4_kernel(
    const float* __restrict__ A, int n,
    const float* __restrict__ W0, const float* __restrict__ b0, float* __restrict__ C0,
    const float* __restrict__ W1, const float* __restrict__ b1, float* __restrict__ C1,
    const float* __restrict__ W2, const float* __restrict__ b2, float* __restrict__ C2,
    const float* __restrict__ W3, const float* __restrict__ b3, float* __restrict__ C3)
{
    const float* W; const float* bias; float* C;
    if (blockIdx.y == 0)      { W = W0; bias = b0; C = C0; }
    else if (blockIdx.y == 1) { W = W1; bias = b1; C = C1; }
    else if (blockIdx.y == 2) { W = W2; bias = b2; C = C2; }
    else                      { W = W3; bias = b3; C = C3; }

    __shared__ u64   As2[16][132];   // duplicated (a,a) per row, [k][row]
    __shared__ float Ws[16][132];    // [k][col]

    int t = threadIdx.x;
    int tx = t & 15;       // col group: cols tx*4..tx*4+3 and +64
    int ty = t >> 4;       // row group: rows ty*4..ty*4+3 and +64
    int row0 = blockIdx.x * 128;

    // acc[rc][cc][r][c2]: packed pair of cols (tx*4 + cc*64 + 2*c2, +1)
    u64 acc[2][2][4][2];
    {
#pragma unroll
        for (int cc = 0; cc < 2; cc++)
#pragma unroll
            for (int c2 = 0; c2 < 2; c2++) {
                u64 bp = pack2(bias[tx * 4 + cc * 64 + 2 * c2],
                               bias[tx * 4 + cc * 64 + 2 * c2 + 1]);
#pragma unroll
                for (int rc = 0; rc < 2; rc++)
#pragma unroll
                    for (int r = 0; r < 4; r++)
                        acc[rc][cc][r][c2] = bp;
            }
    }

    for (int kc = 0; kc < 128; kc += 16) {
        // stage A tile transposed + duplicated: As2[k][r] = (a, a)
#pragma unroll
        for (int i = 0; i < 2; i++) {
            int idx = t + i * 256;           // 0..511
            int r = idx >> 2;                // 0..127
            int c4 = (idx & 3) * 4;          // 0,4,8,12
            float4 av = make_float4(0.f, 0.f, 0.f, 0.f);
            int grow = row0 + r;
            if (grow < n)
                av = *reinterpret_cast<const float4*>(A + (size_t)grow * 128 + kc + c4);
            As2[c4 + 0][r] = pack2(av.x, av.x);
            As2[c4 + 1][r] = pack2(av.y, av.y);
            As2[c4 + 2][r] = pack2(av.z, av.z);
            As2[c4 + 3][r] = pack2(av.w, av.w);
        }
        // stage W tile: 16 k x 128 cols
#pragma unroll
        for (int i = 0; i < 2; i++) {
            int idx = t + i * 256;
            int kr = idx >> 5;               // 0..15
            int c4 = (idx & 31) * 4;
            float4 wv = *reinterpret_cast<const float4*>(W + (size_t)(kc + kr) * 128 + c4);
            *reinterpret_cast<float4*>(&Ws[kr][c4]) = wv;
        }
        __syncthreads();

#pragma unroll
        for (int kk = 0; kk < 16; kk++) {
            // a-splats: rows ty*4..+3 and +64 (2 u64 per LDS.128)
            ulonglong2 a00 = *reinterpret_cast<ulonglong2*>(&As2[kk][ty * 4]);
            ulonglong2 a01 = *reinterpret_cast<ulonglong2*>(&As2[kk][ty * 4 + 2]);
            ulonglong2 a10 = *reinterpret_cast<ulonglong2*>(&As2[kk][ty * 4 + 64]);
            ulonglong2 a11 = *reinterpret_cast<ulonglong2*>(&As2[kk][ty * 4 + 66]);
            u64 ap[2][4] = {{a00.x, a00.y, a01.x, a01.y},
                            {a10.x, a10.y, a11.x, a11.y}};
            // w natural col pairs: float4 = 2 f32x2 pairs
            u64 w[2][2];
            {
                ulonglong2 wv0 = *reinterpret_cast<ulonglong2*>(&Ws[kk][tx * 4]);
                ulonglong2 wv1 = *reinterpret_cast<ulonglong2*>(&Ws[kk][tx * 4 + 64]);
                w[0][0] = wv0.x; w[0][1] = wv0.y;
                w[1][0] = wv1.x; w[1][1] = wv1.y;
            }
#pragma unroll
            for (int r = 0; r < 4; r++)
#pragma unroll
                for (int cc = 0; cc < 2; cc++)
#pragma unroll
                    for (int c2 = 0; c2 < 2; c2++) {
                        fma2(acc[0][cc][r][c2], ap[0][r], w[cc][c2]);
                        fma2(acc[1][cc][r][c2], ap[1][r], w[cc][c2]);
                    }
        }
        __syncthreads();
    }

#pragma unroll
    for (int rc = 0; rc < 2; rc++)
#pragma unroll
        for (int r = 0; r < 4; r++) {
            int grow = row0 + ty * 4 + rc * 64 + r;
            if (grow < n) {
#pragma unroll
                for (int cc = 0; cc < 2; cc++) {
                    float x0, x1, x2, x3;
                    unpack2(acc[rc][cc][r][0], x0, x1);
                    unpack2(acc[rc][cc][r][1], x2, x3);
                    *reinterpret_cast<float4*>(C + (size_t)grow * 128 + tx * 4 + cc * 64)
                        = make_float4(x0, x1, x2, x3);
                }
            }
        }
}

// ---------------- fused attention gather (no edge-embedding materialization) -
// alpha_h = q_h.k_h + ef . qe[:,h],  qe[i][h] = sum_c We[i][16h+c] q[16h+c]
// out = (sum ea*v + (sum ea*ef) @ We) / denom + skip, relu
// warp per destination node, 2-edge software pipeline; NH = 8 or 1.
template <int NH>
__global__ void __launch_bounds__(256) node_attn_kernel(
    const float* __restrict__ Q, const float* __restrict__ K, const float* __restrict__ V,
    const float* __restrict__ EF, const float* __restrict__ We,
    const float* __restrict__ SK, float* __restrict__ outp, float scale)
{
    __shared__ float We_sm[32][132];      // We[32][128], padded
    __shared__ float wbuf[8][2][288];     // per-warp scratch

    int t = threadIdx.x;
    for (int i = t; i < 32 * 32; i += 256) {
        int row = i >> 5, c4 = (i & 31) * 4;
        float4 wv = *reinterpret_cast<const float4*>(We + (size_t)row * 128 + c4);
        *reinterpret_cast<float4*>(&We_sm[row][c4]) = wv;
    }
    __syncthreads();

    int w = t >> 5;
    int l = t & 31;
    int n = blockIdx.x * 8 + w;
    if (n >= NN) return;

    // stage q row, compute qe (lane l plays We-row i=l)
    float4 q4 = reinterpret_cast<const float4*>(Q + (size_t)n * 128)[l];
    *reinterpret_cast<float4*>(&wbuf[w][0][l * 4]) = q4;
    __syncwarp();

    float qe[NH];
    if (NH == 8) {
#pragma unroll
        for (int h = 0; h < 8; h++) {
            float a = 0.f;
#pragma unroll
            for (int c = 0; c < 16; c += 4) {
                float4 wv = *reinterpret_cast<float4*>(&We_sm[l][16 * h + c]);
                float4 qv = *reinterpret_cast<float4*>(&wbuf[w][0][16 * h + c]);
                a += wv.x * qv.x + wv.y * qv.y + wv.z * qv.z + wv.w * qv.w;
            }
            qe[h] = a;
        }
    } else {
        float a = 0.f;
#pragma unroll
        for (int c = 0; c < 128; c += 4) {
            float4 wv = *reinterpret_cast<float4*>(&We_sm[l][c]);
            float4 qv = *reinterpret_cast<float4*>(&wbuf[w][0][c]);
            a += wv.x * qv.x + wv.y * qv.y + wv.z * qv.z + wv.w * qv.w;
        }
        qe[0] = a;
    }
    __syncwarp();

    float4 accv = make_float4(0.f, 0.f, 0.f, 0.f);
    float wef[NH];
#pragma unroll
    for (int h = 0; h < NH; h++) wef[h] = 0.f;
    float den = 0.f;
    int hm = (NH == 8) ? (l >> 2) : 0;
    int p4 = l & 3;

    int p0 = g_rowptr[n], p1 = g_rowptr[n + 1];
    int p = p0;

    // ---- pairwise main loop: 2 edges in flight ----
    for (; p + 2 <= p1; p += 2) {
        int2 se0 = g_csr[p];
        int2 se1 = g_csr[p + 1];
        float4 k4a = reinterpret_cast<const float4*>(K + (size_t)se0.x * 128)[l];
        float4 v4a = reinterpret_cast<const float4*>(V + (size_t)se0.x * 128)[l];
        float4 k4b = reinterpret_cast<const float4*>(K + (size_t)se1.x * 128)[l];
        float4 v4b = reinterpret_cast<const float4*>(V + (size_t)se1.x * 128)[l];
        float efa  = EF[(size_t)se0.y * 32 + l];
        float efb  = EF[(size_t)se1.y * 32 + l];

        float sa = q4.x * k4a.x + q4.y * k4a.y + q4.z * k4a.z + q4.w * k4a.w;
        float sb = q4.x * k4b.x + q4.y * k4b.y + q4.z * k4b.z + q4.w * k4b.w;
        if (NH == 8) {
            sa += __shfl_xor_sync(0xffffffffu, sa, 1);
            sb += __shfl_xor_sync(0xffffffffu, sb, 1);
            sa += __shfl_xor_sync(0xffffffffu, sa, 2);
            sb += __shfl_xor_sync(0xffffffffu, sb, 2);
            float* pb0 = &wbuf[w][0][0];
            float* pb1 = &wbuf[w][1][0];
#pragma unroll
            for (int h = 0; h < 8; h++) {
                pb0[l * 9 + h] = efa * qe[h];
                pb1[l * 9 + h] = efb * qe[h];
            }
            __syncwarp();
            float tsa = 0.f, tsb = 0.f;
#pragma unroll
            for (int j = 0; j < 8; j++) {
                tsa += pb0[(p4 * 8 + j) * 9 + hm];
                tsb += pb1[(p4 * 8 + j) * 9 + hm];
            }
            tsa += __shfl_xor_sync(0xffffffffu, tsa, 1);
            tsb += __shfl_xor_sync(0xffffffffu, tsb, 1);
            tsa += __shfl_xor_sync(0xffffffffu, tsa, 2);
            tsb += __shfl_xor_sync(0xffffffffu, tsb, 2);
            float eaa = __expf((sa + tsa) * scale);
            float eab = __expf((sb + tsb) * scale);
            den += eaa + eab;
            accv.x += eaa * v4a.x + eab * v4b.x;
            accv.y += eaa * v4a.y + eab * v4b.y;
            accv.z += eaa * v4a.z + eab * v4b.z;
            accv.w += eaa * v4a.w + eab * v4b.w;
#pragma unroll
            for (int h = 0; h < 8; h++) {
                float e1 = __shfl_sync(0xffffffffu, eaa, h * 4);
                float e2 = __shfl_sync(0xffffffffu, eab, h * 4);
                wef[h] += e1 * efa + e2 * efb;
            }
            __syncwarp();
        } else {
            sa += efa * qe[0];
            sb += efb * qe[0];
#pragma unroll
            for (int off = 16; off > 0; off >>= 1) {
                sa += __shfl_xor_sync(0xffffffffu, sa, off);
                sb += __shfl_xor_sync(0xffffffffu, sb, off);
            }
            float eaa = __expf(sa * scale);
            float eab = __expf(sb * scale);
            den += eaa + eab;
            accv.x += eaa * v4a.x + eab * v4b.x;
            accv.y += eaa * v4a.y + eab * v4b.y;
            accv.z += eaa * v4a.z + eab * v4b.z;
            accv.w += eaa * v4a.w + eab * v4b.w;
            wef[0] += eaa * efa + eab * efb;
        }
    }

    // ---- remainder edge ----
    if (p < p1) {
        int2 se = g_csr[p];
        float4 k4 = reinterpret_cast<const float4*>(K + (size_t)se.x * 128)[l];
        float4 v4 = reinterpret_cast<const float4*>(V + (size_t)se.x * 128)[l];
        float ef  = EF[(size_t)se.y * 32 + l];

        float s = q4.x * k4.x + q4.y * k4.y + q4.z * k4.z + q4.w * k4.w;
        if (NH == 8) {
            s += __shfl_xor_sync(0xffffffffu, s, 1);
            s += __shfl_xor_sync(0xffffffffu, s, 2);
            float* pb = &wbuf[w][0][0];
#pragma unroll
            for (int h = 0; h < 8; h++) pb[l * 9 + h] = ef * qe[h];
            __syncwarp();
            float ts = 0.f;
#pragma unroll
            for (int j = 0; j < 8; j++) ts += pb[(p4 * 8 + j) * 9 + hm];
            ts += __shfl_xor_sync(0xffffffffu, ts, 1);
            ts += __shfl_xor_sync(0xffffffffu, ts, 2);
            float ea = __expf((s + ts) * scale);
            den += ea;
            accv.x += ea * v4.x; accv.y += ea * v4.y;
            accv.z += ea * v4.z; accv.w += ea * v4.w;
#pragma unroll
            for (int h = 0; h < 8; h++) {
                float eah = __shfl_sync(0xffffffffu, ea, h * 4);
                wef[h] += eah * ef;
            }
            __syncwarp();
        } else {
            s += ef * qe[0];
#pragma unroll
            for (int off = 16; off > 0; off >>= 1)
                s += __shfl_xor_sync(0xffffffffu, s, off);
            float ea = __expf(s * scale);
            den += ea;
            accv.x += ea * v4.x; accv.y += ea * v4.y;
            accv.z += ea * v4.z; accv.w += ea * v4.w;
            wef[0] += ea * ef;
        }
    }

    // epilogue: out = (accv + wef @ We) / den + skip, relu
    float4 oe = make_float4(0.f, 0.f, 0.f, 0.f);
    if (NH == 8) {
        __syncwarp();
#pragma unroll
        for (int h = 0; h < 8; h++) wbuf[w][0][l * 9 + h] = wef[h];
        __syncwarp();
#pragma unroll 8
        for (int i = 0; i < 32; i++) {
            float wv = wbuf[w][0][i * 9 + hm];
            float4 we4 = *reinterpret_cast<float4*>(&We_sm[i][l * 4]);
            oe.x += wv * we4.x; oe.y += wv * we4.y;
            oe.z += wv * we4.z; oe.w += wv * we4.w;
        }
    } else {
#pragma unroll 8
        for (int i = 0; i < 32; i++) {
            float wv = __shfl_sync(0xffffffffu, wef[0], i);
            float4 we4 = *reinterpret_cast<float4*>(&We_sm[i][l * 4]);
            oe.x += wv * we4.x; oe.y += wv * we4.y;
            oe.z += wv * we4.z; oe.w += wv * we4.w;
        }
    }

    float4 sk = reinterpret_cast<const float4*>(SK + (size_t)n * 128)[l];
    float inv = 1.f / fmaxf(den, 1e-16f);
    float4 o;
    o.x = fmaxf((accv.x + oe.x) * inv + sk.x, 0.f);
    o.y = fmaxf((accv.y + oe.y) * inv + sk.y, 0.f);
    o.z = fmaxf((accv.z + oe.z) * inv + sk.z, 0.f);
    o.w = fmaxf((accv.w + oe.w) * inv + sk.w, 0.f);
    reinterpret_cast<float4*>(outp + (size_t)n * 128)[l] = o;
}

// ---------------- launch -----------------------------------------------------
extern "C" void kernel_launch(void* const* d_in, const int* in_sizes, int n_in,
                              void* d_out, int out_size) {
    const float* x          = (const float*)d_in[0];
    const void*  edge_index = d_in[1];
    const float* edge_feats = (const float*)d_in[2];
    const float* Wq1 = (const float*)d_in[3];
    const float* bq1 = (const float*)d_in[4];
    const float* Wk1 = (const float*)d_in[5];
    const float* bk1 = (const float*)d_in[6];
    const float* Wv1 = (const float*)d_in[7];
    const float* bv1 = (const float*)d_in[8];
    const float* We1 = (const float*)d_in[9];
    const float* Ws1 = (const float*)d_in[10];
    const float* bs1 = (const float*)d_in[11];
    const float* Wq2 = (const float*)d_in[12];
    const float* bq2 = (const float*)d_in[13];
    const float* Wk2 = (const float*)d_in[14];
    const float* bk2 = (const float*)d_in[15];
    const float* Wv2 = (const float*)d_in[16];
    const float* bv2 = (const float*)d_in[17];
    const float* We2 = (const float*)d_in[18];
    const float* Ws2 = (const float*)d_in[19];
    const float* bs2 = (const float*)d_in[20];
    float* out = (float*)d_out;

    float* Qp; cudaGetSymbolAddress((void**)&Qp, g_Q);
    float* Kp; cudaGetSymbolAddress((void**)&Kp, g_K);
    float* Vp; cudaGetSymbolAddress((void**)&Vp, g_V);
    float* Sp; cudaGetSymbolAddress((void**)&Sp, g_S);
    float* Hp; cudaGetSymbolAddress((void**)&Hp, g_H);

    const int NAGRID = (NN + 7) / 8;               // warp-per-node, 8 warps/block
    dim3 g4((NN + 127) / 128, 4);

    // setup + layer-1 GEMM early (GEMM depends only on x; keeps gemm4 in the
    // ncu capture slot)
    detect_idx_kernel<<<1, 256>>>((const unsigned int*)edge_index);
    extract_idx_kernel<<<(EE + 255) / 256, 256>>>(edge_index);
    zero_deg_kernel<<<(NN + 255) / 256, 256>>>();
    gemm4_kernel<<<g4, 256>>>(x, NN,
                              Wq1, bq1, Qp,
                              Wk1, bk1, Kp,
                              Wv1, bv1, Vp,
                              Ws1, bs1, Sp);
    hist_kernel<<<(EE + 255) / 256, 256>>>();
    csr_scan_kernel<<<1, 1024>>>();
    csr_scatter_kernel<<<(EE + 255) / 256, 256>>>();

    // ---- layer 1 attention ----
    node_attn_kernel<8><<<NAGRID, 256>>>(Qp, Kp, Vp, edge_feats, We1, Sp, Hp, 0.25f);

    // ---- layer 2 ----
    gemm4_kernel<<<g4, 256>>>(Hp, NN,
                              Wq2, bq2, Qp,
                              Wk2, bk2, Kp,
                              Wv2, bv2, Vp,
                              Ws2, bs2, Sp);
    node_attn_kernel<1><<<NAGRID, 256>>>(Qp, Kp, Vp, edge_feats, We2, Sp, out,
                                         0.08838834764831845f);
}

// round 14
// speedup vs baseline: 1.0847x; 1.0847x over previous
#include <cuda_runtime.h>
#include <cuda_bf16.h>
#include <math.h>

// Problem constants (fixed by the reference)
#define NN 50000
#define EE 400000
// IN=128, H1=128, HEADS=8, HID=16, OUT=128, EDIM=32

typedef unsigned long long u64;

__device__ __forceinline__ u64 pack2(float lo, float hi) {
    u64 r;
    asm("mov.b64 %0, {%1, %2};" : "=l"(r) : "r"(__float_as_uint(lo)), "r"(__float_as_uint(hi)));
    return r;
}
__device__ __forceinline__ void unpack2(u64 v, float& lo, float& hi) {
    unsigned int a, b;
    asm("mov.b64 {%0, %1}, %2;" : "=r"(a), "=r"(b) : "l"(v));
    lo = __uint_as_float(a); hi = __uint_as_float(b);
}
__device__ __forceinline__ void fma2(u64& d, u64 a, u64 b) {
    asm("fma.rn.f32x2 %0, %1, %2, %3;" : "=l"(d) : "l"(a), "l"(b), "l"(d));
}

// ---------------- scratch (static device globals; no allocation) -------------
static __device__ float g_Q[NN * 128];
static __device__ float g_K[NN * 128];
static __device__ float g_V[NN * 128];
static __device__ float g_S[NN * 128];          // skip term x@Ws+bs
static __device__ float g_H[NN * 128];          // layer1 output h
static __device__ int   g_src[EE];
static __device__ int   g_dst[EE];
static __device__ int   g_deg[NN];
static __device__ int   g_rowptr[NN + 1];
static __device__ int   g_cursor[NN];
static __device__ int2  g_csr[EE];              // (src, eid)
static __device__ int   g_is64;

// ---------------- dtype sniffing for edge_index ------------------------------
__global__ void detect_idx_kernel(const unsigned int* __restrict__ p) {
    __shared__ unsigned int sh[256];
    unsigned int acc = 0;
    for (int i = threadIdx.x; i < 4096; i += 256) acc |= p[2 * i + 1];
    sh[threadIdx.x] = acc;
    __syncthreads();
    for (int s = 128; s > 0; s >>= 1) {
        if (threadIdx.x < s) sh[threadIdx.x] |= sh[threadIdx.x + s];
        __syncthreads();
    }
    if (threadIdx.x == 0) g_is64 = (sh[0] == 0u) ? 1 : 0;
}

__global__ void extract_idx_kernel(const void* __restrict__ p) {
    int e = blockIdx.x * blockDim.x + threadIdx.x;
    if (e >= EE) return;
    if (g_is64) {
        const long long* q = (const long long*)p;
        g_src[e] = (int)q[e];
        g_dst[e] = (int)q[EE + e];
    } else {
        const int* q = (const int*)p;
        g_src[e] = q[e];
        g_dst[e] = q[EE + e];
    }
}

// ---------------- CSR build --------------------------------------------------
__global__ void zero_deg_kernel() {
    int i = blockIdx.x * blockDim.x + threadIdx.x;
    if (i < NN) g_deg[i] = 0;
}

__global__ void hist_kernel() {
    int e = blockIdx.x * blockDim.x + threadIdx.x;
    if (e < EE) atomicAdd(&g_deg[g_dst[e]], 1);
}

__global__ void __launch_bounds__(1024) csr_scan_kernel() {
    __shared__ int ssum[1024];
    int t = threadIdx.x;
    const int CH = (NN + 1023) / 1024; // 49
    int start = t * CH;
    int s = 0;
    for (int i = 0; i < CH; i++) {
        int idx = start + i;
        if (idx < NN) s += g_deg[idx];
    }
    ssum[t] = s;
    __syncthreads();
    for (int off = 1; off < 1024; off <<= 1) {
        int v = (t >= off) ? ssum[t - off] : 0;
        __syncthreads();
        ssum[t] += v;
        __syncthreads();
    }
    int run = (t == 0) ? 0 : ssum[t - 1];
    for (int i = 0; i < CH; i++) {
        int idx = start + i;
        if (idx < NN) {
            g_rowptr[idx] = run;
            g_cursor[idx] = run;
            run += g_deg[idx];
        }
    }
    if (t == 1023) g_rowptr[NN] = run;
}

__global__ void csr_scatter_kernel() {
    int e = blockIdx.x * blockDim.x + threadIdx.x;
    if (e >= EE) return;
    int d = g_dst[e];
    int pos = atomicAdd(&g_cursor[d], 1);
    g_csr[pos] = make_int2(g_src[e], e);
}

// ---------------- fused node GEMM: 4 outputs, 128x128 tile -------------------
// Pack-free inner loop: A staged in smem as duplicated (a,a) u64 splats;
// W staged as floats, read as natural f32x2 column pairs.
// Per kk: 4 LDS.128 (a) + 2 LDS.128 (w) + 32 FFMA2, no ALU packs.
// __launch_bounds__(256, 2): force <=128 regs so 2 CTAs/SM stay resident
// (R9 lesson: 130 regs -> 1 CTA/SM -> occupancy collapse).
__global__ void __launch_bounds__(256, 2) gemm4_kernel(
    const float* __restrict__ A, int n,
    const float* __restrict__ W0, const float* __restrict__ b0, float* __restrict__ C0,
    const float* __restrict__ W1, const float* __restrict__ b1, float* __restrict__ C1,
    const float* __restrict__ W2, const float* __restrict__ b2, float* __restrict__ C2,
    const float* __restrict__ W3, const float* __restrict__ b3, float* __restrict__ C3)
{
    const float* W; const float* bias; float* C;
    if (blockIdx.y == 0)      { W = W0; bias = b0; C = C0; }
    else if (blockIdx.y == 1) { W = W1; bias = b1; C = C1; }
    else if (blockIdx.y == 2) { W = W2; bias = b2; C = C2; }
    else                      { W = W3; bias = b3; C = C3; }

    __shared__ u64   As2[16][132];   // duplicated (a,a) per row, [k][row]
    __shared__ float Ws[16][132];    // [k][col]

    int t = threadIdx.x;
    int tx = t & 15;       // col group: cols tx*4..tx*4+3 and +64
    int ty = t >> 4;       // row group: rows ty*4..ty*4+3 and +64
    int row0 = blockIdx.x * 128;

    // acc[rc][cc][r][c2]: packed pair of cols (tx*4 + cc*64 + 2*c2, +1)
    u64 acc[2][2][4][2];
    {
#pragma unroll
        for (int cc = 0; cc < 2; cc++)
#pragma unroll
            for (int c2 = 0; c2 < 2; c2++) {
                u64 bp = pack2(bias[tx * 4 + cc * 64 + 2 * c2],
                               bias[tx * 4 + cc * 64 + 2 * c2 + 1]);
#pragma unroll
                for (int rc = 0; rc < 2; rc++)
#pragma unroll
                    for (int r = 0; r < 4; r++)
                        acc[rc][cc][r][c2] = bp;
            }
    }

    for (int kc = 0; kc < 128; kc += 16) {
        // stage A tile transposed + duplicated: As2[k][r] = (a, a)
#pragma unroll
        for (int i = 0; i < 2; i++) {
            int idx = t + i * 256;           // 0..511
            int r = idx >> 2;                // 0..127
            int c4 = (idx & 3) * 4;          // 0,4,8,12
            float4 av = make_float4(0.f, 0.f, 0.f, 0.f);
            int grow = row0 + r;
            if (grow < n)
                av = *reinterpret_cast<const float4*>(A + (size_t)grow * 128 + kc + c4);
            As2[c4 + 0][r] = pack2(av.x, av.x);
            As2[c4 + 1][r] = pack2(av.y, av.y);
            As2[c4 + 2][r] = pack2(av.z, av.z);
            As2[c4 + 3][r] = pack2(av.w, av.w);
        }
        // stage W tile: 16 k x 128 cols
#pragma unroll
        for (int i = 0; i < 2; i++) {
            int idx = t + i * 256;
            int kr = idx >> 5;               // 0..15
            int c4 = (idx & 31) * 4;
            float4 wv = *reinterpret_cast<const float4*>(W + (size_t)(kc + kr) * 128 + c4);
            *reinterpret_cast<float4*>(&Ws[kr][c4]) = wv;
        }
        __syncthreads();

#pragma unroll
        for (int kk = 0; kk < 16; kk++) {
            // a-splats: rows ty*4..+3 and +64 (2 u64 per LDS.128)
            ulonglong2 a00 = *reinterpret_cast<ulonglong2*>(&As2[kk][ty * 4]);
            ulonglong2 a01 = *reinterpret_cast<ulonglong2*>(&As2[kk][ty * 4 + 2]);
            ulonglong2 a10 = *reinterpret_cast<ulonglong2*>(&As2[kk][ty * 4 + 64]);
            ulonglong2 a11 = *reinterpret_cast<ulonglong2*>(&As2[kk][ty * 4 + 66]);
            u64 ap[2][4] = {{a00.x, a00.y, a01.x, a01.y},
                            {a10.x, a10.y, a11.x, a11.y}};
            // w natural col pairs: float4 = 2 f32x2 pairs
            u64 w[2][2];
            {
                ulonglong2 wv0 = *reinterpret_cast<ulonglong2*>(&Ws[kk][tx * 4]);
                ulonglong2 wv1 = *reinterpret_cast<ulonglong2*>(&Ws[kk][tx * 4 + 64]);
                w[0][0] = wv0.x; w[0][1] = wv0.y;
                w[1][0] = wv1.x; w[1][1] = wv1.y;
            }
#pragma unroll
            for (int r = 0; r < 4; r++)
#pragma unroll
                for (int cc = 0; cc < 2; cc++)
#pragma unroll
                    for (int c2 = 0; c2 < 2; c2++) {
                        fma2(acc[0][cc][r][c2], ap[0][r], w[cc][c2]);
                        fma2(acc[1][cc][r][c2], ap[1][r], w[cc][c2]);
                    }
        }
        __syncthreads();
    }

#pragma unroll
    for (int rc = 0; rc < 2; rc++)
#pragma unroll
        for (int r = 0; r < 4; r++) {
            int grow = row0 + ty * 4 + rc * 64 + r;
            if (grow < n) {
#pragma unroll
                for (int cc = 0; cc < 2; cc++) {
                    float x0, x1, x2, x3;
                    unpack2(acc[rc][cc][r][0], x0, x1);
                    unpack2(acc[rc][cc][r][1], x2, x3);
                    *reinterpret_cast<float4*>(C + (size_t)grow * 128 + tx * 4 + cc * 64)
                        = make_float4(x0, x1, x2, x3);
                }
            }
        }
}

// ---------------- fused attention gather (no edge-embedding materialization) -
// alpha_h = q_h.k_h + ef . qe[:,h],  qe[i][h] = sum_c We[i][16h+c] q[16h+c]
// out = (sum ea*v + (sum ea*ef) @ We) / denom + skip, relu
// warp per destination node, 2-edge software pipeline; NH = 8 or 1.
template <int NH>
__global__ void __launch_bounds__(256) node_attn_kernel(
    const float* __restrict__ Q, const float* __restrict__ K, const float* __restrict__ V,
    const float* __restrict__ EF, const float* __restrict__ We,
    const float* __restrict__ SK, float* __restrict__ outp, float scale)
{
    __shared__ float We_sm[32][132];      // We[32][128], padded
    __shared__ float wbuf[8][2][288];     // per-warp scratch

    int t = threadIdx.x;
    for (int i = t; i < 32 * 32; i += 256) {
        int row = i >> 5, c4 = (i & 31) * 4;
        float4 wv = *reinterpret_cast<const float4*>(We + (size_t)row * 128 + c4);
        *reinterpret_cast<float4*>(&We_sm[row][c4]) = wv;
    }
    __syncthreads();

    int w = t >> 5;
    int l = t & 31;
    int n = blockIdx.x * 8 + w;
    if (n >= NN) return;

    // stage q row, compute qe (lane l plays We-row i=l)
    float4 q4 = reinterpret_cast<const float4*>(Q + (size_t)n * 128)[l];
    *reinterpret_cast<float4*>(&wbuf[w][0][l * 4]) = q4;
    __syncwarp();

    float qe[NH];
    if (NH == 8) {
#pragma unroll
        for (int h = 0; h < 8; h++) {
            float a = 0.f;
#pragma unroll
            for (int c = 0; c < 16; c += 4) {
                float4 wv = *reinterpret_cast<float4*>(&We_sm[l][16 * h + c]);
                float4 qv = *reinterpret_cast<float4*>(&wbuf[w][0][16 * h + c]);
                a += wv.x * qv.x + wv.y * qv.y + wv.z * qv.z + wv.w * qv.w;
            }
            qe[h] = a;
        }
    } else {
        float a = 0.f;
#pragma unroll
        for (int c = 0; c < 128; c += 4) {
            float4 wv = *reinterpret_cast<float4*>(&We_sm[l][c]);
            float4 qv = *reinterpret_cast<float4*>(&wbuf[w][0][c]);
            a += wv.x * qv.x + wv.y * qv.y + wv.z * qv.z + wv.w * qv.w;
        }
        qe[0] = a;
    }
    __syncwarp();

    float4 accv = make_float4(0.f, 0.f, 0.f, 0.f);
    float wef[NH];
#pragma unroll
    for (int h = 0; h < NH; h++) wef[h] = 0.f;
    float den = 0.f;
    int hm = (NH == 8) ? (l >> 2) : 0;
    int p4 = l & 3;

    int p0 = g_rowptr[n], p1 = g_rowptr[n + 1];
    int p = p0;

    // ---- pairwise main loop: 2 edges in flight ----
    for (; p + 2 <= p1; p += 2) {
        int2 se0 = g_csr[p];
        int2 se1 = g_csr[p + 1];
        float4 k4a = reinterpret_cast<const float4*>(K + (size_t)se0.x * 128)[l];
        float4 v4a = reinterpret_cast<const float4*>(V + (size_t)se0.x * 128)[l];
        float4 k4b = reinterpret_cast<const float4*>(K + (size_t)se1.x * 128)[l];
        float4 v4b = reinterpret_cast<const float4*>(V + (size_t)se1.x * 128)[l];
        float efa  = EF[(size_t)se0.y * 32 + l];
        float efb  = EF[(size_t)se1.y * 32 + l];

        float sa = q4.x * k4a.x + q4.y * k4a.y + q4.z * k4a.z + q4.w * k4a.w;
        float sb = q4.x * k4b.x + q4.y * k4b.y + q4.z * k4b.z + q4.w * k4b.w;
        if (NH == 8) {
            sa += __shfl_xor_sync(0xffffffffu, sa, 1);
            sb += __shfl_xor_sync(0xffffffffu, sb, 1);
            sa += __shfl_xor_sync(0xffffffffu, sa, 2);
            sb += __shfl_xor_sync(0xffffffffu, sb, 2);
            float* pb0 = &wbuf[w][0][0];
            float* pb1 = &wbuf[w][1][0];
#pragma unroll
            for (int h = 0; h < 8; h++) {
                pb0[l * 9 + h] = efa * qe[h];
                pb1[l * 9 + h] = efb * qe[h];
            }
            __syncwarp();
            float tsa = 0.f, tsb = 0.f;
#pragma unroll
            for (int j = 0; j < 8; j++) {
                tsa += pb0[(p4 * 8 + j) * 9 + hm];
                tsb += pb1[(p4 * 8 + j) * 9 + hm];
            }
            tsa += __shfl_xor_sync(0xffffffffu, tsa, 1);
            tsb += __shfl_xor_sync(0xffffffffu, tsb, 1);
            tsa += __shfl_xor_sync(0xffffffffu, tsa, 2);
            tsb += __shfl_xor_sync(0xffffffffu, tsb, 2);
            float eaa = __expf((sa + tsa) * scale);
            float eab = __expf((sb + tsb) * scale);
            den += eaa + eab;
            accv.x += eaa * v4a.x + eab * v4b.x;
            accv.y += eaa * v4a.y + eab * v4b.y;
            accv.z += eaa * v4a.z + eab * v4b.z;
            accv.w += eaa * v4a.w + eab * v4b.w;
#pragma unroll
            for (int h = 0; h < 8; h++) {
                float e1 = __shfl_sync(0xffffffffu, eaa, h * 4);
                float e2 = __shfl_sync(0xffffffffu, eab, h * 4);
                wef[h] += e1 * efa + e2 * efb;
            }
            __syncwarp();
        } else {
            sa += efa * qe[0];
            sb += efb * qe[0];
#pragma unroll
            for (int off = 16; off > 0; off >>= 1) {
                sa += __shfl_xor_sync(0xffffffffu, sa, off);
                sb += __shfl_xor_sync(0xffffffffu, sb, off);
            }
            float eaa = __expf(sa * scale);
            float eab = __expf(sb * scale);
            den += eaa + eab;
            accv.x += eaa * v4a.x + eab * v4b.x;
            accv.y += eaa * v4a.y + eab * v4b.y;
            accv.z += eaa * v4a.z + eab * v4b.z;
            accv.w += eaa * v4a.w + eab * v4b.w;
            wef[0] += eaa * efa + eab * efb;
        }
    }

    // ---- remainder edge ----
    if (p < p1) {
        int2 se = g_csr[p];
        float4 k4 = reinterpret_cast<const float4*>(K + (size_t)se.x * 128)[l];
        float4 v4 = reinterpret_cast<const float4*>(V + (size_t)se.x * 128)[l];
        float ef  = EF[(size_t)se.y * 32 + l];

        float s = q4.x * k4.x + q4.y * k4.y + q4.z * k4.z + q4.w * k4.w;
        if (NH == 8) {
            s += __shfl_xor_sync(0xffffffffu, s, 1);
            s += __shfl_xor_sync(0xffffffffu, s, 2);
            float* pb = &wbuf[w][0][0];
#pragma unroll
            for (int h = 0; h < 8; h++) pb[l * 9 + h] = ef * qe[h];
            __syncwarp();
            float ts = 0.f;
#pragma unroll
            for (int j = 0; j < 8; j++) ts += pb[(p4 * 8 + j) * 9 + hm];
            ts += __shfl_xor_sync(0xffffffffu, ts, 1);
            ts += __shfl_xor_sync(0xffffffffu, ts, 2);
            float ea = __expf((s + ts) * scale);
            den += ea;
            accv.x += ea * v4.x; accv.y += ea * v4.y;
            accv.z += ea * v4.z; accv.w += ea * v4.w;
#pragma unroll
            for (int h = 0; h < 8; h++) {
                float eah = __shfl_sync(0xffffffffu, ea, h * 4);
                wef[h] += eah * ef;
            }
            __syncwarp();
        } else {
            s += ef * qe[0];
#pragma unroll
            for (int off = 16; off > 0; off >>= 1)
                s += __shfl_xor_sync(0xffffffffu, s, off);
            float ea = __expf(s * scale);
            den += ea;
            accv.x += ea * v4.x; accv.y += ea * v4.y;
            accv.z += ea * v4.z; accv.w += ea * v4.w;
            wef[0] += ea * ef;
        }
    }

    // epilogue: out = (accv + wef @ We) / den + skip, relu
    float4 oe = make_float4(0.f, 0.f, 0.f, 0.f);
    if (NH == 8) {
        __syncwarp();
#pragma unroll
        for (int h = 0; h < 8; h++) wbuf[w][0][l * 9 + h] = wef[h];
        __syncwarp();
#pragma unroll 8
        for (int i = 0; i < 32; i++) {
            float wv = wbuf[w][0][i * 9 + hm];
            float4 we4 = *reinterpret_cast<float4*>(&We_sm[i][l * 4]);
            oe.x += wv * we4.x; oe.y += wv * we4.y;
            oe.z += wv * we4.z; oe.w += wv * we4.w;
        }
    } else {
#pragma unroll 8
        for (int i = 0; i < 32; i++) {
            float wv = __shfl_sync(0xffffffffu, wef[0], i);
            float4 we4 = *reinterpret_cast<float4*>(&We_sm[i][l * 4]);
            oe.x += wv * we4.x; oe.y += wv * we4.y;
            oe.z += wv * we4.z; oe.w += wv * we4.w;
        }
    }

    float4 sk = reinterpret_cast<const float4*>(SK + (size_t)n * 128)[l];
    float inv = 1.f / fmaxf(den, 1e-16f);
    float4 o;
    o.x = fmaxf((accv.x + oe.x) * inv + sk.x, 0.f);
    o.y = fmaxf((accv.y + oe.y) * inv + sk.y, 0.f);
    o.z = fmaxf((accv.z + oe.z) * inv + sk.z, 0.f);
    o.w = fmaxf((accv.w + oe.w) * inv + sk.w, 0.f);
    reinterpret_cast<float4*>(outp + (size_t)n * 128)[l] = o;
}

// ---------------- launch -----------------------------------------------------
extern "C" void kernel_launch(void* const* d_in, const int* in_sizes, int n_in,
                              void* d_out, int out_size) {
    const float* x          = (const float*)d_in[0];
    const void*  edge_index = d_in[1];
    const float* edge_feats = (const float*)d_in[2];
    const float* Wq1 = (const float*)d_in[3];
    const float* bq1 = (const float*)d_in[4];
    const float* Wk1 = (const float*)d_in[5];
    const float* bk1 = (const float*)d_in[6];
    const float* Wv1 = (const float*)d_in[7];
    const float* bv1 = (const float*)d_in[8];
    const float* We1 = (const float*)d_in[9];
    const float* Ws1 = (const float*)d_in[10];
    const float* bs1 = (const float*)d_in[11];
    const float* Wq2 = (const float*)d_in[12];
    const float* bq2 = (const float*)d_in[13];
    const float* Wk2 = (const float*)d_in[14];
    const float* bk2 = (const float*)d_in[15];
    const float* Wv2 = (const float*)d_in[16];
    const float* bv2 = (const float*)d_in[17];
    const float* We2 = (const float*)d_in[18];
    const float* Ws2 = (const float*)d_in[19];
    const float* bs2 = (const float*)d_in[20];
    float* out = (float*)d_out;

    float* Qp; cudaGetSymbolAddress((void**)&Qp, g_Q);
    float* Kp; cudaGetSymbolAddress((void**)&Kp, g_K);
    float* Vp; cudaGetSymbolAddress((void**)&Vp, g_V);
    float* Sp; cudaGetSymbolAddress((void**)&Sp, g_S);
    float* Hp; cudaGetSymbolAddress((void**)&Hp, g_H);

    const int NAGRID = (NN + 7) / 8;               // warp-per-node, 8 warps/block
    dim3 g4((NN + 127) / 128, 4);

    // setup + layer-1 GEMM early (GEMM depends only on x; keeps gemm4 in the
    // ncu capture slot)
    detect_idx_kernel<<<1, 256>>>((const unsigned int*)edge_index);
    extract_idx_kernel<<<(EE + 255) / 256, 256>>>(edge_index);
    zero_deg_kernel<<<(NN + 255) / 256, 256>>>();
    gemm4_kernel<<<g4, 256>>>(x, NN,
                              Wq1, bq1, Qp,
                              Wk1, bk1, Kp,
                              Wv1, bv1, Vp,
                              Ws1, bs1, Sp);
    hist_kernel<<<(EE + 255) / 256, 256>>>();
    csr_scan_kernel<<<1, 1024>>>();
    csr_scatter_kernel<<<(EE + 255) / 256, 256>>>();

    // ---- layer 1 attention ----
    node_attn_kernel<8><<<NAGRID, 256>>>(Qp, Kp, Vp, edge_feats, We1, Sp, Hp, 0.25f);

    // ---- layer 2 ----
    gemm4_kernel<<<g4, 256>>>(Hp, NN,
                              Wq2, bq2, Qp,
                              Wk2, bk2, Kp,
                              Wv2, bv2, Vp,
                              Ws2, bs2, Sp);
    node_attn_kernel<1><<<NAGRID, 256>>>(Qp, Kp, Vp, edge_feats, We2, Sp, out,
                                         0.08838834764831845f);
}

// round 15
// speedup vs baseline: 1.1279x; 1.0398x over previous
#include <cuda_runtime.h>
#include <cuda_bf16.h>
#include <math.h>

// Problem constants (fixed by the reference)
#define NN 50000
#define EE 400000
// IN=128, H1=128, HEADS=8, HID=16, OUT=128, EDIM=32

typedef unsigned long long u64;

__device__ __forceinline__ u64 pack2(float lo, float hi) {
    u64 r;
    asm("mov.b64 %0, {%1, %2};" : "=l"(r) : "r"(__float_as_uint(lo)), "r"(__float_as_uint(hi)));
    return r;
}
__device__ __forceinline__ void unpack2(u64 v, float& lo, float& hi) {
    unsigned int a, b;
    asm("mov.b64 {%0, %1}, %2;" : "=r"(a), "=r"(b) : "l"(v));
    lo = __uint_as_float(a); hi = __uint_as_float(b);
}
__device__ __forceinline__ void fma2(u64& d, u64 a, u64 b) {
    asm("fma.rn.f32x2 %0, %1, %2, %3;" : "=l"(d) : "l"(a), "l"(b), "l"(d));
}

// ---------------- scratch (static device globals; no allocation) -------------
static __device__ float g_Q[NN * 128];
static __device__ float g_K[NN * 128];
static __device__ float g_V[NN * 128];
static __device__ float g_S[NN * 128];          // skip term x@Ws+bs
static __device__ float g_H[NN * 128];          // layer1 output h
static __device__ float g_efc[(size_t)EE * 32]; // edge feats permuted into CSR order
static __device__ int   g_src[EE];
static __device__ int   g_dst[EE];
static __device__ int   g_deg[NN];
static __device__ int   g_rowptr[NN + 1];
static __device__ int   g_cursor[NN];
static __device__ int   g_csr_src[EE];          // src per CSR slot
static __device__ int   g_pos[EE];              // CSR slot per original edge
static __device__ int   g_is64;

// ---------------- dtype sniffing for edge_index ------------------------------
__global__ void detect_idx_kernel(const unsigned int* __restrict__ p) {
    __shared__ unsigned int sh[256];
    unsigned int acc = 0;
    for (int i = threadIdx.x; i < 4096; i += 256) acc |= p[2 * i + 1];
    sh[threadIdx.x] = acc;
    __syncthreads();
    for (int s = 128; s > 0; s >>= 1) {
        if (threadIdx.x < s) sh[threadIdx.x] |= sh[threadIdx.x + s];
        __syncthreads();
    }
    if (threadIdx.x == 0) g_is64 = (sh[0] == 0u) ? 1 : 0;
}

// extract indices + zero degree array (fused)
__global__ void extract_zero_kernel(const void* __restrict__ p) {
    int e = blockIdx.x * blockDim.x + threadIdx.x;
    if (e < NN) g_deg[e] = 0;
    if (e >= EE) return;
    if (g_is64) {
        const long long* q = (const long long*)p;
        g_src[e] = (int)q[e];
        g_dst[e] = (int)q[EE + e];
    } else {
        const int* q = (const int*)p;
        g_src[e] = q[e];
        g_dst[e] = q[EE + e];
    }
}

__global__ void hist_kernel() {
    int e = blockIdx.x * blockDim.x + threadIdx.x;
    if (e < EE) atomicAdd(&g_deg[g_dst[e]], 1);
}

__global__ void __launch_bounds__(1024) csr_scan_kernel() {
    __shared__ int ssum[1024];
    int t = threadIdx.x;
    const int CH = (NN + 1023) / 1024; // 49
    int start = t * CH;
    int s = 0;
    for (int i = 0; i < CH; i++) {
        int idx = start + i;
        if (idx < NN) s += g_deg[idx];
    }
    ssum[t] = s;
    __syncthreads();
    for (int off = 1; off < 1024; off <<= 1) {
        int v = (t >= off) ? ssum[t - off] : 0;
        __syncthreads();
        ssum[t] += v;
        __syncthreads();
    }
    int run = (t == 0) ? 0 : ssum[t - 1];
    for (int i = 0; i < CH; i++) {
        int idx = start + i;
        if (idx < NN) {
            g_rowptr[idx] = run;
            g_cursor[idx] = run;
            run += g_deg[idx];
        }
    }
    if (t == 1023) g_rowptr[NN] = run;
}

__global__ void csr_scatter_kernel() {
    int e = blockIdx.x * blockDim.x + threadIdx.x;
    if (e >= EE) return;
    int d = g_dst[e];
    int pos = atomicAdd(&g_cursor[d], 1);
    g_csr_src[pos] = g_src[e];
    g_pos[e] = pos;
}

// permute edge feats into CSR order: warp per edge, coalesced both sides
__global__ void __launch_bounds__(256) ef_permute_kernel(const float* __restrict__ EF) {
    int e = (blockIdx.x * blockDim.x + threadIdx.x) >> 5;
    if (e >= EE) return;
    int l = threadIdx.x & 31;
    int pos = g_pos[e];
    g_efc[(size_t)pos * 32 + l] = EF[(size_t)e * 32 + l];
}

// ---------------- fused node GEMM: 4 outputs, 128x128 tile -------------------
// R8 packed inner loop (known best): float smem tiles; per kk:
// 2 LDS.128 (A) + 4 LDS.64 (W pairs) + 8 pack movs + 32 FFMA2; 6 crossbar phases.
// __launch_bounds__(256,2) guards the 128-reg / 2-CTA residency cliff.
__global__ void __launch_bounds__(256, 2) gemm4_kernel(
    const float* __restrict__ A, int n,
    const float* __restrict__ W0, const float* __restrict__ b0, float* __restrict__ C0,
    const float* __restrict__ W1, const float* __restrict__ b1, float* __restrict__ C1,
    const float* __restrict__ W2, const float* __restrict__ b2, float* __restrict__ C2,
    const float* __restrict__ W3, const float* __restrict__ b3, float* __restrict__ C3)
{
    const float* W; const float* bias; float* C;
    if (blockIdx.y == 0)      { W = W0; bias = b0; C = C0; }
    else if (blockIdx.y == 1) { W = W1; bias = b1; C = C1; }
    else if (blockIdx.y == 2) { W = W2; bias = b2; C = C2; }
    else                      { W = W3; bias = b3; C = C3; }

    __shared__ float As[16][132];
    __shared__ float Ws[16][132];

    int t = threadIdx.x;
    int tx = t & 15;       // col group: cols tx*4..tx*4+3 and +64
    int ty = t >> 4;       // row group: rows ty*4..ty*4+3 and +64
    int row0 = blockIdx.x * 128;

    // acc[rc][cc][r][c2]: packed pair of cols (tx*4 + cc*64 + 2*c2, +1)
    u64 acc[2][2][4][2];
    {
#pragma unroll
        for (int cc = 0; cc < 2; cc++)
#pragma unroll
            for (int c2 = 0; c2 < 2; c2++) {
                u64 bp = pack2(bias[tx * 4 + cc * 64 + 2 * c2],
                               bias[tx * 4 + cc * 64 + 2 * c2 + 1]);
#pragma unroll
                for (int rc = 0; rc < 2; rc++)
#pragma unroll
                    for (int r = 0; r < 4; r++)
                        acc[rc][cc][r][c2] = bp;
            }
    }

    for (int kc = 0; kc < 128; kc += 16) {
        // stage A tile transposed: As[k][row]
#pragma unroll
        for (int i = 0; i < 2; i++) {
            int idx = t + i * 256;           // 0..511
            int r = idx >> 2;                // 0..127
            int c4 = (idx & 3) * 4;          // 0,4,8,12
            float4 av = make_float4(0.f, 0.f, 0.f, 0.f);
            int grow = row0 + r;
            if (grow < n)
                av = *reinterpret_cast<const float4*>(A + (size_t)grow * 128 + kc + c4);
            As[c4 + 0][r] = av.x;
            As[c4 + 1][r] = av.y;
            As[c4 + 2][r] = av.z;
            As[c4 + 3][r] = av.w;
        }
        // stage W tile: 16 k x 128 cols
#pragma unroll
        for (int i = 0; i < 2; i++) {
            int idx = t + i * 256;
            int kr = idx >> 5;               // 0..15
            int c4 = (idx & 31) * 4;
            float4 wv = *reinterpret_cast<const float4*>(W + (size_t)(kc + kr) * 128 + c4);
            *reinterpret_cast<float4*>(&Ws[kr][c4]) = wv;
        }
        __syncthreads();

#pragma unroll
        for (int kk = 0; kk < 16; kk++) {
            float a0[4], a1[4];
            *reinterpret_cast<float4*>(a0) = *reinterpret_cast<float4*>(&As[kk][ty * 4]);
            *reinterpret_cast<float4*>(a1) = *reinterpret_cast<float4*>(&As[kk][ty * 4 + 64]);
            u64 w[2][2];
            w[0][0] = *reinterpret_cast<u64*>(&Ws[kk][tx * 4]);
            w[0][1] = *reinterpret_cast<u64*>(&Ws[kk][tx * 4 + 2]);
            w[1][0] = *reinterpret_cast<u64*>(&Ws[kk][tx * 4 + 64]);
            w[1][1] = *reinterpret_cast<u64*>(&Ws[kk][tx * 4 + 66]);
#pragma unroll
            for (int r = 0; r < 4; r++) {
                u64 ap0 = pack2(a0[r], a0[r]);
                u64 ap1 = pack2(a1[r], a1[r]);
#pragma unroll
                for (int cc = 0; cc < 2; cc++)
#pragma unroll
                    for (int c2 = 0; c2 < 2; c2++) {
                        fma2(acc[0][cc][r][c2], ap0, w[cc][c2]);
                        fma2(acc[1][cc][r][c2], ap1, w[cc][c2]);
                    }
            }
        }
        __syncthreads();
    }

#pragma unroll
    for (int rc = 0; rc < 2; rc++)
#pragma unroll
        for (int r = 0; r < 4; r++) {
            int grow = row0 + ty * 4 + rc * 64 + r;
            if (grow < n) {
#pragma unroll
                for (int cc = 0; cc < 2; cc++) {
                    float x0, x1, x2, x3;
                    unpack2(acc[rc][cc][r][0], x0, x1);
                    unpack2(acc[rc][cc][r][1], x2, x3);
                    *reinterpret_cast<float4*>(C + (size_t)grow * 128 + tx * 4 + cc * 64)
                        = make_float4(x0, x1, x2, x3);
                }
            }
        }
}

// ---------------- fused attention gather (no edge-embedding materialization) -
// alpha_h = q_h.k_h + ef . qe[:,h],  qe[i][h] = sum_c We[i][16h+c] q[16h+c]
// out = (sum ea*v + (sum ea*ef) @ We) / denom + skip, relu
// Edge feats pre-permuted into CSR order (g_efc) -> sequential streaming reads.
// warp per destination node, 2-edge software pipeline; NH = 8 or 1.
template <int NH>
__global__ void __launch_bounds__(256) node_attn_kernel(
    const float* __restrict__ Q, const float* __restrict__ K, const float* __restrict__ V,
    const float* __restrict__ We,
    const float* __restrict__ SK, float* __restrict__ outp, float scale)
{
    __shared__ float We_sm[32][132];      // We[32][128], padded
    __shared__ float wbuf[8][2][288];     // per-warp scratch

    int t = threadIdx.x;
    for (int i = t; i < 32 * 32; i += 256) {
        int row = i >> 5, c4 = (i & 31) * 4;
        float4 wv = *reinterpret_cast<const float4*>(We + (size_t)row * 128 + c4);
        *reinterpret_cast<float4*>(&We_sm[row][c4]) = wv;
    }
    __syncthreads();

    int w = t >> 5;
    int l = t & 31;
    int n = blockIdx.x * 8 + w;
    if (n >= NN) return;

    // stage q row, compute qe (lane l plays We-row i=l)
    float4 q4 = reinterpret_cast<const float4*>(Q + (size_t)n * 128)[l];
    *reinterpret_cast<float4*>(&wbuf[w][0][l * 4]) = q4;
    __syncwarp();

    float qe[NH];
    if (NH == 8) {
#pragma unroll
        for (int h = 0; h < 8; h++) {
            float a = 0.f;
#pragma unroll
            for (int c = 0; c < 16; c += 4) {
                float4 wv = *reinterpret_cast<float4*>(&We_sm[l][16 * h + c]);
                float4 qv = *reinterpret_cast<float4*>(&wbuf[w][0][16 * h + c]);
                a += wv.x * qv.x + wv.y * qv.y + wv.z * qv.z + wv.w * qv.w;
            }
            qe[h] = a;
        }
    } else {
        float a = 0.f;
#pragma unroll
        for (int c = 0; c < 128; c += 4) {
            float4 wv = *reinterpret_cast<float4*>(&We_sm[l][c]);
            float4 qv = *reinterpret_cast<float4*>(&wbuf[w][0][c]);
            a += wv.x * qv.x + wv.y * qv.y + wv.z * qv.z + wv.w * qv.w;
        }
        qe[0] = a;
    }
    __syncwarp();

    float4 accv = make_float4(0.f, 0.f, 0.f, 0.f);
    float wef[NH];
#pragma unroll
    for (int h = 0; h < NH; h++) wef[h] = 0.f;
    float den = 0.f;
    int hm = (NH == 8) ? (l >> 2) : 0;
    int p4 = l & 3;

    int p0 = g_rowptr[n], p1 = g_rowptr[n + 1];
    int p = p0;

    // ---- pairwise main loop: 2 edges in flight ----
    for (; p + 2 <= p1; p += 2) {
        int s0 = g_csr_src[p];
        int s1 = g_csr_src[p + 1];
        float4 k4a = reinterpret_cast<const float4*>(K + (size_t)s0 * 128)[l];
        float4 v4a = reinterpret_cast<const float4*>(V + (size_t)s0 * 128)[l];
        float4 k4b = reinterpret_cast<const float4*>(K + (size_t)s1 * 128)[l];
        float4 v4b = reinterpret_cast<const float4*>(V + (size_t)s1 * 128)[l];
        float efa  = g_efc[(size_t)p * 32 + l];
        float efb  = g_efc[(size_t)(p + 1) * 32 + l];

        float sa = q4.x * k4a.x + q4.y * k4a.y + q4.z * k4a.z + q4.w * k4a.w;
        float sb = q4.x * k4b.x + q4.y * k4b.y + q4.z * k4b.z + q4.w * k4b.w;
        if (NH == 8) {
            sa += __shfl_xor_sync(0xffffffffu, sa, 1);
            sb += __shfl_xor_sync(0xffffffffu, sb, 1);
            sa += __shfl_xor_sync(0xffffffffu, sa, 2);
            sb += __shfl_xor_sync(0xffffffffu, sb, 2);
            float* pb0 = &wbuf[w][0][0];
            float* pb1 = &wbuf[w][1][0];
#pragma unroll
            for (int h = 0; h < 8; h++) {
                pb0[l * 9 + h] = efa * qe[h];
                pb1[l * 9 + h] = efb * qe[h];
            }
            __syncwarp();
            float tsa = 0.f, tsb = 0.f;
#pragma unroll
            for (int j = 0; j < 8; j++) {
                tsa += pb0[(p4 * 8 + j) * 9 + hm];
                tsb += pb1[(p4 * 8 + j) * 9 + hm];
            }
            tsa += __shfl_xor_sync(0xffffffffu, tsa, 1);
            tsb += __shfl_xor_sync(0xffffffffu, tsb, 1);
            tsa += __shfl_xor_sync(0xffffffffu, tsa, 2);
            tsb += __shfl_xor_sync(0xffffffffu, tsb, 2);
            float eaa = __expf((sa + tsa) * scale);
            float eab = __expf((sb + tsb) * scale);
            den += eaa + eab;
            accv.x += eaa * v4a.x + eab * v4b.x;
            accv.y += eaa * v4a.y + eab * v4b.y;
            accv.z += eaa * v4a.z + eab * v4b.z;
            accv.w += eaa * v4a.w + eab * v4b.w;
#pragma unroll
            for (int h = 0; h < 8; h++) {
                float e1 = __shfl_sync(0xffffffffu, eaa, h * 4);
                float e2 = __shfl_sync(0xffffffffu, eab, h * 4);
                wef[h] += e1 * efa + e2 * efb;
            }
            __syncwarp();
        } else {
            sa += efa * qe[0];
            sb += efb * qe[0];
#pragma unroll
            for (int off = 16; off > 0; off >>= 1) {
                sa += __shfl_xor_sync(0xffffffffu, sa, off);
                sb += __shfl_xor_sync(0xffffffffu, sb, off);
            }
            float eaa = __expf(sa * scale);
            float eab = __expf(sb * scale);
            den += eaa + eab;
            accv.x += eaa * v4a.x + eab * v4b.x;
            accv.y += eaa * v4a.y + eab * v4b.y;
            accv.z += eaa * v4a.z + eab * v4b.z;
            accv.w += eaa * v4a.w + eab * v4b.w;
            wef[0] += eaa * efa + eab * efb;
        }
    }

    // ---- remainder edge ----
    if (p < p1) {
        int s0 = g_csr_src[p];
        float4 k4 = reinterpret_cast<const float4*>(K + (size_t)s0 * 128)[l];
        float4 v4 = reinterpret_cast<const float4*>(V + (size_t)s0 * 128)[l];
        float ef  = g_efc[(size_t)p * 32 + l];

        float s = q4.x * k4.x + q4.y * k4.y + q4.z * k4.z + q4.w * k4.w;
        if (NH == 8) {
            s += __shfl_xor_sync(0xffffffffu, s, 1);
            s += __shfl_xor_sync(0xffffffffu, s, 2);
            float* pb = &wbuf[w][0][0];
#pragma unroll
            for (int h = 0; h < 8; h++) pb[l * 9 + h] = ef * qe[h];
            __syncwarp();
            float ts = 0.f;
#pragma unroll
            for (int j = 0; j < 8; j++) ts += pb[(p4 * 8 + j) * 9 + hm];
            ts += __shfl_xor_sync(0xffffffffu, ts, 1);
            ts += __shfl_xor_sync(0xffffffffu, ts, 2);
            float ea = __expf((s + ts) * scale);
            den += ea;
            accv.x += ea * v4.x; accv.y += ea * v4.y;
            accv.z += ea * v4.z; accv.w += ea * v4.w;
#pragma unroll
            for (int h = 0; h < 8; h++) {
                float eah = __shfl_sync(0xffffffffu, ea, h * 4);
                wef[h] += eah * ef;
            }
            __syncwarp();
        } else {
            s += ef * qe[0];
#pragma unroll
            for (int off = 16; off > 0; off >>= 1)
                s += __shfl_xor_sync(0xffffffffu, s, off);
            float ea = __expf(s * scale);
            den += ea;
            accv.x += ea * v4.x; accv.y += ea * v4.y;
            accv.z += ea * v4.z; accv.w += ea * v4.w;
            wef[0] += ea * ef;
        }
    }

    // epilogue: out = (accv + wef @ We) / den + skip, relu
    float4 oe = make_float4(0.f, 0.f, 0.f, 0.f);
    if (NH == 8) {
        __syncwarp();
#pragma unroll
        for (int h = 0; h < 8; h++) wbuf[w][0][l * 9 + h] = wef[h];
        __syncwarp();
#pragma unroll 8
        for (int i = 0; i < 32; i++) {
            float wv = wbuf[w][0][i * 9 + hm];
            float4 we4 = *reinterpret_cast<float4*>(&We_sm[i][l * 4]);
            oe.x += wv * we4.x; oe.y += wv * we4.y;
            oe.z += wv * we4.z; oe.w += wv * we4.w;
        }
    } else {
#pragma unroll 8
        for (int i = 0; i < 32; i++) {
            float wv = __shfl_sync(0xffffffffu, wef[0], i);
            float4 we4 = *reinterpret_cast<float4*>(&We_sm[i][l * 4]);
            oe.x += wv * we4.x; oe.y += wv * we4.y;
            oe.z += wv * we4.z; oe.w += wv * we4.w;
        }
    }

    float4 sk = reinterpret_cast<const float4*>(SK + (size_t)n * 128)[l];
    float inv = 1.f / fmaxf(den, 1e-16f);
    float4 o;
    o.x = fmaxf((accv.x + oe.x) * inv + sk.x, 0.f);
    o.y = fmaxf((accv.y + oe.y) * inv + sk.y, 0.f);
    o.z = fmaxf((accv.z + oe.z) * inv + sk.z, 0.f);
    o.w = fmaxf((accv.w + oe.w) * inv + sk.w, 0.f);
    reinterpret_cast<float4*>(outp + (size_t)n * 128)[l] = o;
}

// ---------------- launch -----------------------------------------------------
extern "C" void kernel_launch(void* const* d_in, const int* in_sizes, int n_in,
                              void* d_out, int out_size) {
    const float* x          = (const float*)d_in[0];
    const void*  edge_index = d_in[1];
    const float* edge_feats = (const float*)d_in[2];
    const float* Wq1 = (const float*)d_in[3];
    const float* bq1 = (const float*)d_in[4];
    const float* Wk1 = (const float*)d_in[5];
    const float* bk1 = (const float*)d_in[6];
    const float* Wv1 = (const float*)d_in[7];
    const float* bv1 = (const float*)d_in[8];
    const float* We1 = (const float*)d_in[9];
    const float* Ws1 = (const float*)d_in[10];
    const float* bs1 = (const float*)d_in[11];
    const float* Wq2 = (const float*)d_in[12];
    const float* bq2 = (const float*)d_in[13];
    const float* Wk2 = (const float*)d_in[14];
    const float* bk2 = (const float*)d_in[15];
    const float* Wv2 = (const float*)d_in[16];
    const float* bv2 = (const float*)d_in[17];
    const float* We2 = (const float*)d_in[18];
    const float* Ws2 = (const float*)d_in[19];
    const float* bs2 = (const float*)d_in[20];
    float* out = (float*)d_out;

    float* Qp; cudaGetSymbolAddress((void**)&Qp, g_Q);
    float* Kp; cudaGetSymbolAddress((void**)&Kp, g_K);
    float* Vp; cudaGetSymbolAddress((void**)&Vp, g_V);
    float* Sp; cudaGetSymbolAddress((void**)&Sp, g_S);
    float* Hp; cudaGetSymbolAddress((void**)&Hp, g_H);

    const int NAGRID = (NN + 7) / 8;               // warp-per-node, 8 warps/block
    dim3 g4((NN + 127) / 128, 4);

    // setup; gemm4 stays 4th launch (ncu capture slot)
    detect_idx_kernel<<<1, 256>>>((const unsigned int*)edge_index);
    extract_zero_kernel<<<(EE + 255) / 256, 256>>>(edge_index);
    hist_kernel<<<(EE + 255) / 256, 256>>>();
    gemm4_kernel<<<g4, 256>>>(x, NN,
                              Wq1, bq1, Qp,
                              Wk1, bk1, Kp,
                              Wv1, bv1, Vp,
                              Ws1, bs1, Sp);
    csr_scan_kernel<<<1, 1024>>>();
    csr_scatter_kernel<<<(EE + 255) / 256, 256>>>();
    ef_permute_kernel<<<(EE * 32 + 255) / 256, 256>>>(edge_feats);

    // ---- layer 1 attention ----
    node_attn_kernel<8><<<NAGRID, 256>>>(Qp, Kp, Vp, We1, Sp, Hp, 0.25f);

    // ---- layer 2 ----
    gemm4_kernel<<<g4, 256>>>(Hp, NN,
                              Wq2, bq2, Qp,
                              Wk2, bk2, Kp,
                              Wv2, bv2, Vp,
                              Ws2, bs2, Sp);
    node_attn_kernel<1><<<NAGRID, 256>>>(Qp, Kp, Vp, We2, Sp, out,
                                         0.08838834764831845f);
}